// round 17
// baseline (speedup 1.0000x reference)
#include <cuda_runtime.h>
#include <math.h>
#include <stdint.h>

// ---------------- problem dims ----------------
#define NB   16
#define NS   768
#define ND   384
#define NH   12
#define NDK  32
#define NFF  1024
#define NL   6
#define NML  768
#define NNC  10
#define NBS  (NB*NS)          // 12288 rows
#define QLD  1152             // fused QKV row stride
#define NREL (2*NML-1)        // 1535

// ---------------- scratch ----------------
#define OFF_X    ((size_t)0)
#define OFF_H    (OFF_X   + (size_t)NBS*ND)
#define OFF_QKV  (OFF_H   + (size_t)NBS*ND)
#define OFF_A    (OFF_QKV + (size_t)NBS*QLD)
#define OFF_FF   (OFF_A   + (size_t)NBS*ND)
#define OFF_PT   (OFF_FF  + (size_t)NBS*NFF)
#define OFF_PS   (OFF_PT  + (size_t)NBS*384)
#define OFF_PD   (OFF_PS  + (size_t)4*NBS)
#define OFF_C1   (OFF_PD  + (size_t)NB*4*ND)
#define OFF_C2   (OFF_C1  + (size_t)NB*ND)
#define OFF_PW   (OFF_C2  + (size_t)NB*192)
#define OFF_WQKV (OFF_PW  + (size_t)384*384)
#define OFF_BQKV (OFF_WQKV + (size_t)NL*ND*QLD)
#define OFF_WOT  (OFF_BQKV + (size_t)NL*QLD)
#define OFF_F1T  (OFF_WOT + (size_t)NL*ND*ND)
#define OFF_F2T  (OFF_F1T + (size_t)NL*ND*NFF)
#define OFF_RELT (OFF_F2T + (size_t)NL*NFF*ND)
#define SCRATCH_TOTAL (OFF_RELT + (size_t)NL*NREL*NDK)

static __device__ float g_scratch[SCRATCH_TOTAL];

// ---------------- tf32 / cp.async helpers ----------------
__device__ __forceinline__ float f2tf(float f) {
    uint32_t u;
    asm("cvt.rna.tf32.f32 %0, %1;" : "=r"(u) : "f"(f));
    return __uint_as_float(u);
}

__device__ __forceinline__ void mma_tf32(float* c, const float* a, const float* b) {
    asm volatile(
        "mma.sync.aligned.m16n8k8.row.col.f32.tf32.tf32.f32 "
        "{%0,%1,%2,%3}, {%4,%5,%6,%7}, {%8,%9}, {%0,%1,%2,%3};"
        : "+f"(c[0]), "+f"(c[1]), "+f"(c[2]), "+f"(c[3])
        : "r"(__float_as_uint(a[0])), "r"(__float_as_uint(a[1])),
          "r"(__float_as_uint(a[2])), "r"(__float_as_uint(a[3])),
          "r"(__float_as_uint(b[0])), "r"(__float_as_uint(b[1])));
}

__device__ __forceinline__ void cp_async16(void* sdst, const void* gsrc) {
    uint32_t s = (uint32_t)__cvta_generic_to_shared(sdst);
    asm volatile("cp.async.cg.shared.global [%0], [%1], 16;" :: "r"(s), "l"(gsrc));
}
#define CP_COMMIT() asm volatile("cp.async.commit_group;")
#define CP_WAIT0()  asm volatile("cp.async.wait_group 0;" ::: "memory")

// ---------------- embed (float4) ----------------
__global__ void embed_kernel(const float* __restrict__ te, const float* __restrict__ pe,
                             const int* __restrict__ ids, float* __restrict__ x) {
    int row = blockIdx.x;
    int s   = row % NS;
    int id  = ids[row];
    const float4* tp = (const float4*)(te + (size_t)id * ND);
    const float4* pp = (const float4*)(pe + (size_t)s * ND);
    float4* xp = (float4*)(x + (size_t)row * ND);
    for (int i = threadIdx.x; i < 96; i += 128) {
        float4 a = tp[i], b = pp[i];
        xp[i] = make_float4(a.x + b.x, a.y + b.y, a.z + b.z, a.w + b.w);
    }
}

// ---------------- weight packers (pre-rounded to tf32 bits) ----------------
__global__ void round_copy(const float* __restrict__ src, float* __restrict__ dst, int n) {
    int i = blockIdx.x * 256 + threadIdx.x;
    if (i < n) dst[i] = f2tf(src[i]);
}

__global__ void pack_pool_w(const float* __restrict__ pw1, float* __restrict__ Wp) {
    int idx = blockIdx.x * 256 + threadIdx.x;
    if (idx < 384 * 384) {
        int k = idx / 384, c = idx % 384;
        int h = c / 96, j = c % 96;
        Wp[idx] = f2tf(pw1[((size_t)h * 384 + k) * 96 + j]);
    }
}

__global__ void pack_qkv_w(const float* __restrict__ wq, const float* __restrict__ wk,
                           const float* __restrict__ wv, float* __restrict__ Wf) {
    int idx = blockIdx.x * 256 + threadIdx.x;
    if (idx >= NL * ND * QLD) return;
    int l   = idx / (ND * QLD);
    int rem = idx - l * (ND * QLD);
    int k   = rem / QLD;
    int c   = rem - k * QLD;
    int sel = c / ND;
    int col = c - sel * ND;
    const float* src = (sel == 0) ? wq : (sel == 1) ? wk : wv;
    Wf[idx] = f2tf(src[((size_t)l * ND + k) * ND + col]);
}

__global__ void pack_qkv_b(const float* __restrict__ bq, const float* __restrict__ bk,
                           const float* __restrict__ bv, float* __restrict__ Bf) {
    int idx = blockIdx.x * 256 + threadIdx.x;
    if (idx >= NL * QLD) return;
    int l = idx / QLD;
    int c = idx - l * QLD;
    int sel = c / ND;
    int col = c - sel * ND;
    const float* src = (sel == 0) ? bq : (sel == 1) ? bk : bv;
    Bf[idx] = src[l * ND + col];
}

// ---------------- layernorm: warp per row, outputs rounded to tf32 ----------------
__global__ void ln_kernel(const float* __restrict__ in, float* __restrict__ out,
                          const float* __restrict__ g, const float* __restrict__ b) {
    int row  = blockIdx.x * 8 + (threadIdx.x >> 5);
    int lane = threadIdx.x & 31;
    const float4* p = (const float4*)(in + (size_t)row * ND);
    float4 v[3];
    float s = 0.f;
    #pragma unroll
    for (int i = 0; i < 3; i++) {
        v[i] = p[lane + i * 32];
        s += v[i].x + v[i].y + v[i].z + v[i].w;
    }
    #pragma unroll
    for (int o = 16; o > 0; o >>= 1) s += __shfl_xor_sync(0xffffffffu, s, o);
    float mean = s * (1.f / ND);
    float vs = 0.f;
    #pragma unroll
    for (int i = 0; i < 3; i++) {
        float a0 = v[i].x - mean, a1 = v[i].y - mean;
        float a2 = v[i].z - mean, a3 = v[i].w - mean;
        vs += a0 * a0 + a1 * a1 + a2 * a2 + a3 * a3;
    }
    #pragma unroll
    for (int o = 16; o > 0; o >>= 1) vs += __shfl_xor_sync(0xffffffffu, vs, o);
    float inv = rsqrtf(vs * (1.f / ND) + 1e-5f);
    float4* o4 = (float4*)(out + (size_t)row * ND);
    #pragma unroll
    for (int i = 0; i < 3; i++) {
        float4 gv = ((const float4*)g)[lane + i * 32];
        float4 bv = ((const float4*)b)[lane + i * 32];
        float4 o;
        o.x = f2tf((v[i].x - mean) * inv * gv.x + bv.x);
        o.y = f2tf((v[i].y - mean) * inv * gv.y + bv.y);
        o.z = f2tf((v[i].z - mean) * inv * gv.z + bv.z);
        o.w = f2tf((v[i].w - mean) * inv * gv.w + bv.w);
        o4[lane + i * 32] = o;
    }
}

// ================= tf32 TC GEMM: 256x128 tile, BK=16, 256 threads =================
// Inputs pre-rounded to tf32 bits (A by producers, W by pack kernels).
// B staged via cp.async. EPI: 0 none+round, 1 gelu+round, 2 residual, 3 tanh
#define GSTRIDE 136
#define GEMM_SMEM_WORDS (2*4096 + 2*16*GSTRIDE)
#define GEMM_SMEM_BYTES (GEMM_SMEM_WORDS * 4)

template<int EPI>
__global__ void __launch_bounds__(256, 1)
gemm_tc_kernel(const float* __restrict__ A, const float* __restrict__ W,
               const float* __restrict__ bias, const float* __restrict__ res,
               float* __restrict__ C, int M, int N, int K) {
    extern __shared__ __align__(16) float dsm[];
    float* As2 = dsm;                       // [2][4096]
    float* Bsf = dsm + 8192;                // [2][16][GSTRIDE]

    const int t    = threadIdx.x;
    const int lane = t & 31;
    const int warp = t >> 5;
    const int wn   = (warp & 1) * 64;
    const int gid  = lane >> 2;
    const int tig  = lane & 3;
    const int brow = blockIdx.y * 256;
    const int bcol = blockIdx.x * 128;

    const int ar  = t;
    const int asw = ((ar & 7) >> 1) & 3;
    const int amb = (ar >> 4) * 128 + (ar & 7) * 16 + ((ar >> 3) & 1);
    const int bkr = t >> 5;
    const int bc  = lane * 4;

    const int afrag = (warp >> 1) * 512 + gid * 16 + ((tig ^ ((gid >> 1) & 3)) << 2);

    const float* Ap = A + (size_t)(brow + ar) * K;

    float acc[4][8][4];
    #pragma unroll
    for (int i = 0; i < 4; i++)
        #pragma unroll
        for (int j = 0; j < 8; j++)
            #pragma unroll
            for (int r = 0; r < 4; r++) acc[i][j][r] = 0.f;

    const int ntiles = K / 16;

    // ---- prologue: tile 0 -> buf 0 ----
    {
        #pragma unroll
        for (int q = 0; q < 4; q++) {
            float4 aq = *(const float4*)&Ap[q * 4];
            const float* ae = &aq.x;
            int base = (q >> 1) * 2048 + amb + (q & 1) * 2;
            #pragma unroll
            for (int j = 0; j < 4; j++)
                As2[base + ((j ^ asw) << 2)] = ae[j];
        }
        cp_async16(&Bsf[bkr * GSTRIDE + bc],       &W[(size_t)bkr * N + bcol + bc]);
        cp_async16(&Bsf[(bkr + 8) * GSTRIDE + bc], &W[(size_t)(bkr + 8) * N + bcol + bc]);
        CP_COMMIT();
    }
    CP_WAIT0();
    __syncthreads();

    for (int tt = 0; tt < ntiles; tt++) {
        const int cur = tt & 1;
        const int nxt = cur ^ 1;
        const bool more = (tt + 1 < ntiles);
        float4 apre[4];
        if (more) {
            const int k0 = (tt + 1) * 16;
            float* Bn = Bsf + nxt * (16 * GSTRIDE);
            cp_async16(&Bn[bkr * GSTRIDE + bc],       &W[(size_t)(k0 + bkr) * N + bcol + bc]);
            cp_async16(&Bn[(bkr + 8) * GSTRIDE + bc], &W[(size_t)(k0 + bkr + 8) * N + bcol + bc]);
            CP_COMMIT();
            #pragma unroll
            for (int q = 0; q < 4; q++) apre[q] = *(const float4*)&Ap[k0 + q * 4];
        }
        const float* Ab = As2 + cur * 4096;
        const float* Bb = Bsf + cur * (16 * GSTRIDE);
        #pragma unroll
        for (int ks = 0; ks < 2; ks++) {
            float a[4][4], b[8][2];
            #pragma unroll
            for (int mt = 0; mt < 4; mt++) {
                float4 av = *(const float4*)&Ab[ks * 2048 + mt * 128 + afrag];
                a[mt][0] = av.x; a[mt][1] = av.y; a[mt][2] = av.z; a[mt][3] = av.w;
            }
            #pragma unroll
            for (int nt = 0; nt < 8; nt++) {
                const int n0 = wn + nt * 8 + gid;
                b[nt][0] = Bb[(ks * 8 + tig) * GSTRIDE + n0];
                b[nt][1] = Bb[(ks * 8 + tig + 4) * GSTRIDE + n0];
            }
            #pragma unroll
            for (int mt = 0; mt < 4; mt++)
                #pragma unroll
                for (int nt = 0; nt < 8; nt++)
                    mma_tf32(acc[mt][nt], a[mt], b[nt]);
        }
        if (more) {
            float* An = As2 + nxt * 4096;
            #pragma unroll
            for (int q = 0; q < 4; q++) {
                const float* ae = &apre[q].x;
                int base = (q >> 1) * 2048 + amb + (q & 1) * 2;
                #pragma unroll
                for (int j = 0; j < 4; j++)
                    An[base + ((j ^ asw) << 2)] = ae[j];
            }
        }
        CP_WAIT0();
        __syncthreads();
    }

    // ---- epilogue ----
    const int wm = (warp >> 1) * 64;
    #pragma unroll
    for (int mt = 0; mt < 4; mt++) {
        const int r0 = brow + wm + mt * 16 + gid;
        #pragma unroll
        for (int nt = 0; nt < 8; nt++) {
            const int c0 = bcol + wn + nt * 8 + tig * 2;
            float bx = bias[c0], by = bias[c0 + 1];
            float v00 = acc[mt][nt][0] + bx;
            float v01 = acc[mt][nt][1] + by;
            float v10 = acc[mt][nt][2] + bx;
            float v11 = acc[mt][nt][3] + by;
            if (EPI == 0) {
                v00 = f2tf(v00); v01 = f2tf(v01);
                v10 = f2tf(v10); v11 = f2tf(v11);
            } else if (EPI == 1) {
                v00 = f2tf(0.5f * v00 * (1.f + erff(v00 * 0.70710678118654752f)));
                v01 = f2tf(0.5f * v01 * (1.f + erff(v01 * 0.70710678118654752f)));
                v10 = f2tf(0.5f * v10 * (1.f + erff(v10 * 0.70710678118654752f)));
                v11 = f2tf(0.5f * v11 * (1.f + erff(v11 * 0.70710678118654752f)));
            } else if (EPI == 2) {
                float2 r0v = *(const float2*)&res[(size_t)r0 * N + c0];
                float2 r1v = *(const float2*)&res[(size_t)(r0 + 8) * N + c0];
                v00 += r0v.x; v01 += r0v.y; v10 += r1v.x; v11 += r1v.y;
            } else if (EPI == 3) {
                v00 = tanhf(v00); v01 = tanhf(v01);
                v10 = tanhf(v10); v11 = tanhf(v11);
            }
            *(float2*)&C[(size_t)r0 * N + c0]       = make_float2(v00, v01);
            *(float2*)&C[(size_t)(r0 + 8) * N + c0] = make_float2(v10, v11);
        }
    }
}

// ---------------- small guarded SGEMM (classifier) ----------------
template<int EPI>
__global__ void gemm_kernel(const float* __restrict__ A, const float* __restrict__ W,
                            const float* __restrict__ bias,
                            float* __restrict__ C, int M, int N, int K) {
    __shared__ float As[16][65];
    __shared__ float Bs[16][64];
    const int brow = blockIdx.y * 64;
    const int bcol = blockIdx.x * 64;
    const int t  = threadIdx.x;
    const int ty = t >> 4, tx = t & 15;
    float acc[4][4] = {};
    for (int k0 = 0; k0 < K; k0 += 16) {
        #pragma unroll
        for (int l = t; l < 1024; l += 256) {
            int r = l >> 4, kk = l & 15;
            int gr = brow + r;
            As[kk][r] = (gr < M && k0 + kk < K) ? A[(size_t)gr * K + k0 + kk] : 0.f;
        }
        #pragma unroll
        for (int l = t; l < 1024; l += 256) {
            int kk = l >> 6, c = l & 63;
            int gc = bcol + c;
            Bs[kk][c] = (gc < N && k0 + kk < K) ? W[(size_t)(k0 + kk) * N + gc] : 0.f;
        }
        __syncthreads();
        #pragma unroll
        for (int kk = 0; kk < 16; kk++) {
            float a[4], bvals[4];
            #pragma unroll
            for (int i = 0; i < 4; i++) a[i] = As[kk][ty * 4 + i];
            #pragma unroll
            for (int j = 0; j < 4; j++) bvals[j] = Bs[kk][tx * 4 + j];
            #pragma unroll
            for (int i = 0; i < 4; i++)
                #pragma unroll
                for (int j = 0; j < 4; j++)
                    acc[i][j] += a[i] * bvals[j];
        }
        __syncthreads();
    }
    #pragma unroll
    for (int i = 0; i < 4; i++) {
        int row = brow + ty * 4 + i;
        if (row >= M) continue;
        #pragma unroll
        for (int j = 0; j < 4; j++) {
            int col = bcol + tx * 4 + j;
            if (col >= N) continue;
            float v = acc[i][j] + bias[col];
            if (EPI == 1) v = 0.5f * v * (1.f + erff(v * 0.70710678118654752f));
            else if (EPI == 3) v = tanhf(v);
            C[(size_t)row * N + col] = v;
        }
    }
}

// ================= tensor-core flash attention: 4 warps x 32 q-rows, reg-pipelined =================
// Q/K/V/rel already tf32-rounded by producers; only probs rounded in-kernel.
#define WSTRIDE 100
#define ATT_SMEM_WORDS 27968
#define ATT_SMEM_BYTES (ATT_SMEM_WORDS * 4)

__global__ void __launch_bounds__(128, 2)
attn_tc_kernel(const float* __restrict__ q, const float* __restrict__ k,
               const float* __restrict__ v, const float* __restrict__ rel,
               const int* __restrict__ ids, float* __restrict__ out) {
    extern __shared__ float sm[];
    float* Qs = sm;                   // [32][132]
    float* Ks = sm + 4224;            // [32][68]
    float* Rs = sm + 6400;            // [32][200]
    float* Vs = sm + 12800;           // [64][36]
    float* WS = sm + 15104;           // [4][32][100]
    int*   Mk = (int*)(sm + 27904);   // [64]

    const int q0 = blockIdx.x * 128;
    const int h  = blockIdx.y;
    const int b  = blockIdx.z;
    const int t    = threadIdx.x;     // 0..127
    const int lane = t & 31;
    const int w    = t >> 5;          // 0..3
    const int gid  = lane >> 2;
    const int tig  = lane & 3;
    float* WSw = WS + w * (32 * WSTRIDE);
    const int j0w = 96 - 32 * w;
    const float scale = 0.17677669529663689f;

    const int kvr = t >> 3;
    const int kvd = (t & 7) * 4;
    const float* kbase = k + ((size_t)(b * NS)) * QLD + h * NDK + (size_t)kvr * QLD + kvd;
    const float* vbase = v + ((size_t)(b * NS)) * QLD + h * NDK + (size_t)kvr * QLD + kvd;

    // ---- load Q tile (transposed; already tf32 bits) ----
    {
        const float* qb = q + ((size_t)(b * NS + q0)) * QLD + h * NDK;
        #pragma unroll
        for (int i = t; i < 1024; i += 128) {
            int r = i >> 3, d0 = (i & 7) * 4;
            float4 x = *(const float4*)&qb[(size_t)r * QLD + d0];
            Qs[(d0 + 0) * 132 + r] = x.x;
            Qs[(d0 + 1) * 132 + r] = x.y;
            Qs[(d0 + 2) * 132 + r] = x.z;
            Qs[(d0 + 3) * 132 + r] = x.w;
        }
    }

    float4 rK[4], rV[4], rR[12];
    int rM = 0;

    // prologue: tile 0
    {
        #pragma unroll
        for (int j = 0; j < 4; j++) {
            rK[j] = *(const float4*)&kbase[(size_t)(j * 16) * QLD];
            rV[j] = *(const float4*)&vbase[(size_t)(j * 16) * QLD];
        }
        #pragma unroll
        for (int j = 0; j < 12; j++) {
            int i = t + j * 128;
            int row = i >> 3, d0 = (i & 7) * 4;
            int g = -q0 + 640 + row;
            if (g > 1534) g = 1534;
            rR[j] = *(const float4*)&rel[(size_t)g * NDK + d0];
        }
        if (t < 64) rM = ids[b * NS + t];
    }
    __syncthreads();   // Qs ready

    float af[2][4][4];
    #pragma unroll
    for (int mt = 0; mt < 2; mt++)
        #pragma unroll
        for (int ks = 0; ks < 4; ks++) {
            int kk = ks * 8 + tig;
            int m0 = w * 32 + mt * 16 + gid;
            af[mt][ks][0] = Qs[kk * 132 + m0];
            af[mt][ks][1] = Qs[kk * 132 + m0 + 8];
            af[mt][ks][2] = Qs[(kk + 4) * 132 + m0];
            af[mt][ks][3] = Qs[(kk + 4) * 132 + m0 + 8];
        }

    // store tile 0 to smem
    {
        #pragma unroll
        for (int j = 0; j < 4; j++) {
            int r = kvr + j * 16;
            Ks[(kvd + 0) * 68 + r] = rK[j].x;
            Ks[(kvd + 1) * 68 + r] = rK[j].y;
            Ks[(kvd + 2) * 68 + r] = rK[j].z;
            Ks[(kvd + 3) * 68 + r] = rK[j].w;
            *(float4*)&Vs[r * 36 + kvd] = rV[j];
        }
        #pragma unroll
        for (int j = 0; j < 12; j++) {
            int i = t + j * 128;
            int row = i >> 3, d0 = (i & 7) * 4;
            Rs[(d0 + 0) * 200 + row] = rR[j].x;
            Rs[(d0 + 1) * 200 + row] = rR[j].y;
            Rs[(d0 + 2) * 200 + row] = rR[j].z;
            Rs[(d0 + 3) * 200 + row] = rR[j].w;
        }
        if (t < 64) Mk[t] = rM;
    }
    __syncthreads();

    float mxs[2][2], lss[2][2];
    float oa[2][4][4];
    #pragma unroll
    for (int mt = 0; mt < 2; mt++) {
        mxs[mt][0] = -INFINITY; mxs[mt][1] = -INFINITY;
        lss[mt][0] = 0.f;       lss[mt][1] = 0.f;
        #pragma unroll
        for (int i = 0; i < 4; i++)
            #pragma unroll
            for (int j = 0; j < 4; j++) oa[mt][i][j] = 0.f;
    }

    for (int k0 = 0; k0 < NS; k0 += 64) {
        const bool more = (k0 + 64 < NS);
        if (more) {
            const int kn = k0 + 64;
            #pragma unroll
            for (int j = 0; j < 4; j++) {
                rK[j] = *(const float4*)&kbase[(size_t)(kn + j * 16) * QLD];
                rV[j] = *(const float4*)&vbase[(size_t)(kn + j * 16) * QLD];
            }
            #pragma unroll
            for (int j = 0; j < 12; j++) {
                int i = t + j * 128;
                int row = i >> 3, d0 = (i & 7) * 4;
                int g = kn - q0 + 640 + row;
                if (g > 1534) g = 1534;
                rR[j] = *(const float4*)&rel[(size_t)g * NDK + d0];
            }
            if (t < 64) rM = ids[b * NS + kn + t];
        }

        // ---- rel-band MMA ----
        #pragma unroll
        for (int chunk = 0; chunk < 3; chunk++) {
            float rc[2][4][4];
            #pragma unroll
            for (int mt = 0; mt < 2; mt++)
                #pragma unroll
                for (int nt = 0; nt < 4; nt++)
                    #pragma unroll
                    for (int e = 0; e < 4; e++) rc[mt][nt][e] = 0.f;
            #pragma unroll
            for (int ks = 0; ks < 4; ks++) {
                int kk = ks * 8 + tig;
                #pragma unroll
                for (int nt = 0; nt < 4; nt++) {
                    int col = j0w + (chunk * 4 + nt) * 8 + gid;
                    float bb[2];
                    bb[0] = Rs[kk * 200 + col];
                    bb[1] = Rs[(kk + 4) * 200 + col];
                    #pragma unroll
                    for (int mt = 0; mt < 2; mt++)
                        mma_tf32(rc[mt][nt], af[mt][ks], bb);
                }
            }
            #pragma unroll
            for (int mt = 0; mt < 2; mt++)
                #pragma unroll
                for (int nt = 0; nt < 4; nt++) {
                    int c0 = (chunk * 4 + nt) * 8 + 2 * tig;
                    int r0 = mt * 16 + gid;
                    WSw[r0 * WSTRIDE + c0]           = rc[mt][nt][0];
                    WSw[r0 * WSTRIDE + c0 + 1]       = rc[mt][nt][1];
                    WSw[(r0 + 8) * WSTRIDE + c0]     = rc[mt][nt][2];
                    WSw[(r0 + 8) * WSTRIDE + c0 + 1] = rc[mt][nt][3];
                }
        }
        __syncwarp();

        // ---- QK MMA ----
        float qa[2][8][4];
        #pragma unroll
        for (int mt = 0; mt < 2; mt++)
            #pragma unroll
            for (int nt = 0; nt < 8; nt++)
                #pragma unroll
                for (int e = 0; e < 4; e++) qa[mt][nt][e] = 0.f;
        #pragma unroll
        for (int ks = 0; ks < 4; ks++) {
            int kk = ks * 8 + tig;
            #pragma unroll
            for (int nt = 0; nt < 8; nt++) {
                int col = nt * 8 + gid;
                float bb[2];
                bb[0] = Ks[kk * 68 + col];
                bb[1] = Ks[(kk + 4) * 68 + col];
                #pragma unroll
                for (int mt = 0; mt < 2; mt++)
                    mma_tf32(qa[mt][nt], af[mt][ks], bb);
            }
        }

        // ---- combine + mask ----
        #pragma unroll
        for (int mt = 0; mt < 2; mt++)
            #pragma unroll
            for (int nt = 0; nt < 8; nt++) {
                int kl0 = nt * 8 + 2 * tig;
                int kl1 = kl0 + 1;
                int rlo = mt * 16 + gid, rhi = rlo + 8;
                bool m0b = (Mk[kl0] == 0), m1b = (Mk[kl1] == 0);
                qa[mt][nt][0] = m0b ? -INFINITY : (qa[mt][nt][0] + WSw[rlo * WSTRIDE + kl0 + 31 - rlo]) * scale;
                qa[mt][nt][1] = m1b ? -INFINITY : (qa[mt][nt][1] + WSw[rlo * WSTRIDE + kl1 + 31 - rlo]) * scale;
                qa[mt][nt][2] = m0b ? -INFINITY : (qa[mt][nt][2] + WSw[rhi * WSTRIDE + kl0 + 31 - rhi]) * scale;
                qa[mt][nt][3] = m1b ? -INFINITY : (qa[mt][nt][3] + WSw[rhi * WSTRIDE + kl1 + 31 - rhi]) * scale;
            }
        __syncwarp();

        // ---- online softmax per m-tile ----
        #pragma unroll
        for (int mt = 0; mt < 2; mt++) {
            float tm_lo = -INFINITY, tm_hi = -INFINITY;
            #pragma unroll
            for (int nt = 0; nt < 8; nt++) {
                tm_lo = fmaxf(tm_lo, fmaxf(qa[mt][nt][0], qa[mt][nt][1]));
                tm_hi = fmaxf(tm_hi, fmaxf(qa[mt][nt][2], qa[mt][nt][3]));
            }
            tm_lo = fmaxf(tm_lo, __shfl_xor_sync(0xffffffffu, tm_lo, 1));
            tm_lo = fmaxf(tm_lo, __shfl_xor_sync(0xffffffffu, tm_lo, 2));
            tm_hi = fmaxf(tm_hi, __shfl_xor_sync(0xffffffffu, tm_hi, 1));
            tm_hi = fmaxf(tm_hi, __shfl_xor_sync(0xffffffffu, tm_hi, 2));

            float nm_lo = fmaxf(mxs[mt][0], tm_lo);
            float nm_hi = fmaxf(mxs[mt][1], tm_hi);
            float c_lo = 1.f, c_hi = 1.f, sum_lo = 0.f, sum_hi = 0.f;
            int rlo = mt * 16 + gid, rhi = rlo + 8;

            if (nm_lo == -INFINITY) {
                #pragma unroll
                for (int nt = 0; nt < 8; nt++) {
                    int c0 = nt * 8 + 2 * tig;
                    WSw[rlo * WSTRIDE + c0] = 0.f; WSw[rlo * WSTRIDE + c0 + 1] = 0.f;
                }
            } else {
                c_lo = __expf(mxs[mt][0] - nm_lo);
                #pragma unroll
                for (int nt = 0; nt < 8; nt++) {
                    int c0 = nt * 8 + 2 * tig;
                    float p0 = __expf(qa[mt][nt][0] - nm_lo);
                    float p1 = __expf(qa[mt][nt][1] - nm_lo);
                    sum_lo += p0 + p1;
                    WSw[rlo * WSTRIDE + c0]     = f2tf(p0);
                    WSw[rlo * WSTRIDE + c0 + 1] = f2tf(p1);
                }
            }
            if (nm_hi == -INFINITY) {
                #pragma unroll
                for (int nt = 0; nt < 8; nt++) {
                    int c0 = nt * 8 + 2 * tig;
                    WSw[rhi * WSTRIDE + c0] = 0.f; WSw[rhi * WSTRIDE + c0 + 1] = 0.f;
                }
            } else {
                c_hi = __expf(mxs[mt][1] - nm_hi);
                #pragma unroll
                for (int nt = 0; nt < 8; nt++) {
                    int c0 = nt * 8 + 2 * tig;
                    float p0 = __expf(qa[mt][nt][2] - nm_hi);
                    float p1 = __expf(qa[mt][nt][3] - nm_hi);
                    sum_hi += p0 + p1;
                    WSw[rhi * WSTRIDE + c0]     = f2tf(p0);
                    WSw[rhi * WSTRIDE + c0 + 1] = f2tf(p1);
                }
            }
            sum_lo += __shfl_xor_sync(0xffffffffu, sum_lo, 1);
            sum_lo += __shfl_xor_sync(0xffffffffu, sum_lo, 2);
            sum_hi += __shfl_xor_sync(0xffffffffu, sum_hi, 1);
            sum_hi += __shfl_xor_sync(0xffffffffu, sum_hi, 2);
            mxs[mt][0] = nm_lo; mxs[mt][1] = nm_hi;
            lss[mt][0] = lss[mt][0] * c_lo + sum_lo;
            lss[mt][1] = lss[mt][1] * c_hi + sum_hi;
            #pragma unroll
            for (int nt = 0; nt < 4; nt++) {
                oa[mt][nt][0] *= c_lo; oa[mt][nt][1] *= c_lo;
                oa[mt][nt][2] *= c_hi; oa[mt][nt][3] *= c_hi;
            }
        }
        __syncwarp();

        // ---- PV MMA ----
        #pragma unroll
        for (int ks = 0; ks < 8; ks++) {
            int kk = ks * 8 + tig;
            float pa[2][4];
            #pragma unroll
            for (int mt = 0; mt < 2; mt++) {
                int r0 = mt * 16 + gid;
                pa[mt][0] = WSw[r0 * WSTRIDE + kk];
                pa[mt][1] = WSw[(r0 + 8) * WSTRIDE + kk];
                pa[mt][2] = WSw[r0 * WSTRIDE + kk + 4];
                pa[mt][3] = WSw[(r0 + 8) * WSTRIDE + kk + 4];
            }
            #pragma unroll
            for (int nt = 0; nt < 4; nt++) {
                int col = nt * 8 + gid;
                float bb[2];
                bb[0] = Vs[kk * 36 + col];
                bb[1] = Vs[(kk + 4) * 36 + col];
                #pragma unroll
                for (int mt = 0; mt < 2; mt++)
                    mma_tf32(oa[mt][nt], pa[mt], bb);
            }
        }

        // ---- commit prefetched tile to smem ----
        if (more) {
            __syncthreads();
            #pragma unroll
            for (int j = 0; j < 4; j++) {
                int r = kvr + j * 16;
                Ks[(kvd + 0) * 68 + r] = rK[j].x;
                Ks[(kvd + 1) * 68 + r] = rK[j].y;
                Ks[(kvd + 2) * 68 + r] = rK[j].z;
                Ks[(kvd + 3) * 68 + r] = rK[j].w;
                *(float4*)&Vs[r * 36 + kvd] = rV[j];
            }
            #pragma unroll
            for (int j = 0; j < 12; j++) {
                int i = t + j * 128;
                int row = i >> 3, d0 = (i & 7) * 4;
                Rs[(d0 + 0) * 200 + row] = rR[j].x;
                Rs[(d0 + 1) * 200 + row] = rR[j].y;
                Rs[(d0 + 2) * 200 + row] = rR[j].z;
                Rs[(d0 + 3) * 200 + row] = rR[j].w;
            }
            if (t < 64) Mk[t] = rM;
            __syncthreads();
        }
    }

    // ---- finalize (rounded: feeds wo GEMM A-path) ----
    #pragma unroll
    for (int mt = 0; mt < 2; mt++) {
        float inv_lo = (lss[mt][0] > 0.f) ? 1.f / lss[mt][0] : 0.f;
        float inv_hi = (lss[mt][1] > 0.f) ? 1.f / lss[mt][1] : 0.f;
        const int rlo = b * NS + q0 + w * 32 + mt * 16 + gid;
        #pragma unroll
        for (int nt = 0; nt < 4; nt++) {
            int col = h * NDK + nt * 8 + 2 * tig;
            out[(size_t)rlo * ND + col]           = f2tf(oa[mt][nt][0] * inv_lo);
            out[(size_t)rlo * ND + col + 1]       = f2tf(oa[mt][nt][1] * inv_lo);
            out[(size_t)(rlo + 8) * ND + col]     = f2tf(oa[mt][nt][2] * inv_hi);
            out[(size_t)(rlo + 8) * ND + col + 1] = f2tf(oa[mt][nt][3] * inv_hi);
        }
    }
}

// ---------------- pooling ----------------
__global__ void pool_score_kernel(const float* __restrict__ tmp, const float* __restrict__ pw2,
                                  const float* __restrict__ pb2, float* __restrict__ scores) {
    int gid = blockIdx.x * (blockDim.x >> 5) + (threadIdx.x >> 5);
    if (gid >= 4 * NBS) return;
    int head = gid / NBS;
    int row  = gid - head * NBS;
    int lane = threadIdx.x & 31;
    const float* p = tmp + (size_t)row * 384 + head * 96;
    float s = 0.f;
    for (int j = lane; j < 96; j += 32) s += p[j] * pw2[head * 96 + j];
    #pragma unroll
    for (int o = 16; o > 0; o >>= 1) s += __shfl_xor_sync(0xffffffffu, s, o);
    if (lane == 0) scores[gid] = s + pb2[head];
}

__global__ void pool_kernel(const float* __restrict__ x, const float* __restrict__ scores,
                            const int* __restrict__ ids, float* __restrict__ pooled) {
    const int head = blockIdx.x;
    const int b    = blockIdx.y;
    __shared__ float ps[NS];
    __shared__ float red[8];
    const float* sc = scores + (size_t)head * NBS + (size_t)b * NS;

    float m = -INFINITY;
    for (int s = threadIdx.x; s < NS; s += 256) {
        float val = (ids[b * NS + s] == 0) ? -INFINITY : sc[s];
        ps[s] = val;
        m = fmaxf(m, val);
    }
    #pragma unroll
    for (int o = 16; o > 0; o >>= 1) m = fmaxf(m, __shfl_xor_sync(0xffffffffu, m, o));
    if ((threadIdx.x & 31) == 0) red[threadIdx.x >> 5] = m;
    __syncthreads();
    float M = -INFINITY;
    #pragma unroll
    for (int i = 0; i < 8; i++) M = fmaxf(M, red[i]);
    __syncthreads();

    float sum = 0.f;
    for (int s = threadIdx.x; s < NS; s += 256) {
        float p = __expf(ps[s] - M);
        ps[s] = p;
        sum += p;
    }
    #pragma unroll
    for (int o = 16; o > 0; o >>= 1) sum += __shfl_xor_sync(0xffffffffu, sum, o);
    if ((threadIdx.x & 31) == 0) red[threadIdx.x >> 5] = sum;
    __syncthreads();
    float T = 0.f;
    #pragma unroll
    for (int i = 0; i < 8; i++) T += red[i];
    __syncthreads();
    float inv = 1.f / T;

    for (int d = threadIdx.x; d < ND; d += 256) {
        float acc = 0.f;
        const float* xp = x + (size_t)b * NS * ND + d;
        for (int s = 0; s < NS; s++) acc += ps[s] * xp[(size_t)s * ND];
        pooled[(size_t)b * (4 * ND) + head * ND + d] = acc * inv;
    }
}

// ---------------- dispatchers ----------------
static void run_big_gemm(const float* A, const float* W, const float* bias, const float* res,
                         float* C, int M, int N, int K, int epi) {
    dim3 grid(N / 128, M / 256);
    switch (epi) {
        case 0: gemm_tc_kernel<0><<<grid, 256, GEMM_SMEM_BYTES>>>(A, W, bias, res, C, M, N, K); break;
        case 1: gemm_tc_kernel<1><<<grid, 256, GEMM_SMEM_BYTES>>>(A, W, bias, res, C, M, N, K); break;
        case 2: gemm_tc_kernel<2><<<grid, 256, GEMM_SMEM_BYTES>>>(A, W, bias, res, C, M, N, K); break;
        case 3: gemm_tc_kernel<3><<<grid, 256, GEMM_SMEM_BYTES>>>(A, W, bias, res, C, M, N, K); break;
    }
}

static void run_small_gemm(const float* A, const float* W, const float* bias,
                           float* C, int M, int N, int K, int epi) {
    dim3 grid((N + 63) / 64, (M + 63) / 64);
    switch (epi) {
        case 0: gemm_kernel<0><<<grid, 256>>>(A, W, bias, C, M, N, K); break;
        case 1: gemm_kernel<1><<<grid, 256>>>(A, W, bias, C, M, N, K); break;
        case 3: gemm_kernel<3><<<grid, 256>>>(A, W, bias, C, M, N, K); break;
    }
}

// ---------------- entry ----------------
extern "C" void kernel_launch(void* const* d_in, const int* in_sizes, int n_in,
                              void* d_out, int out_size) {
    const float* te   = (const float*)d_in[0];
    const float* pe   = (const float*)d_in[1];
    const float* wq   = (const float*)d_in[2];
    const float* bq   = (const float*)d_in[3];
    const float* wk   = (const float*)d_in[4];
    const float* bk   = (const float*)d_in[5];
    const float* wv   = (const float*)d_in[6];
    const float* bv   = (const float*)d_in[7];
    const float* wo   = (const float*)d_in[8];
    const float* bo   = (const float*)d_in[9];
    const float* rel  = (const float*)d_in[10];
    const float* g1   = (const float*)d_in[11];
    const float* b1   = (const float*)d_in[12];
    const float* g2   = (const float*)d_in[13];
    const float* b2   = (const float*)d_in[14];
    const float* fw1  = (const float*)d_in[15];
    const float* fb1  = (const float*)d_in[16];
    const float* fw2  = (const float*)d_in[17];
    const float* fb2  = (const float*)d_in[18];
    const float* fg   = (const float*)d_in[19];
    const float* fbn  = (const float*)d_in[20];
    const float* pw1  = (const float*)d_in[21];
    const float* pb1  = (const float*)d_in[22];
    const float* pw2  = (const float*)d_in[23];
    const float* pb2  = (const float*)d_in[24];
    const float* cw1  = (const float*)d_in[25];
    const float* cb1  = (const float*)d_in[26];
    const float* cw2  = (const float*)d_in[27];
    const float* cb2  = (const float*)d_in[28];
    const float* cw3  = (const float*)d_in[29];
    const float* cb3  = (const float*)d_in[30];
    const int*   ids  = (const int*)d_in[31];

    float* S;
    cudaGetSymbolAddress((void**)&S, g_scratch);
    float* X    = S + OFF_X;
    float* HB   = S + OFF_H;
    float* QKV  = S + OFF_QKV;
    float* AB   = S + OFF_A;
    float* FB   = S + OFF_FF;
    float* PT   = S + OFF_PT;
    float* PS   = S + OFF_PS;
    float* PD   = S + OFF_PD;
    float* C1   = S + OFF_C1;
    float* C2   = S + OFF_C2;
    float* PW   = S + OFF_PW;
    float* WQKV = S + OFF_WQKV;
    float* BQKV = S + OFF_BQKV;
    float* WOT  = S + OFF_WOT;
    float* F1T  = S + OFF_F1T;
    float* F2T  = S + OFF_F2T;
    float* RELT = S + OFF_RELT;

    cudaFuncSetAttribute(attn_tc_kernel,
                         cudaFuncAttributeMaxDynamicSharedMemorySize, ATT_SMEM_BYTES);
    cudaFuncSetAttribute(gemm_tc_kernel<0>,
                         cudaFuncAttributeMaxDynamicSharedMemorySize, GEMM_SMEM_BYTES);
    cudaFuncSetAttribute(gemm_tc_kernel<1>,
                         cudaFuncAttributeMaxDynamicSharedMemorySize, GEMM_SMEM_BYTES);
    cudaFuncSetAttribute(gemm_tc_kernel<2>,
                         cudaFuncAttributeMaxDynamicSharedMemorySize, GEMM_SMEM_BYTES);
    cudaFuncSetAttribute(gemm_tc_kernel<3>,
                         cudaFuncAttributeMaxDynamicSharedMemorySize, GEMM_SMEM_BYTES);

    // packs (all weights pre-rounded to tf32 bits)
    pack_qkv_w<<<(NL * ND * QLD + 255) / 256, 256>>>(wq, wk, wv, WQKV);
    pack_qkv_b<<<(NL * QLD + 255) / 256, 256>>>(bq, bk, bv, BQKV);
    pack_pool_w<<<576, 256>>>(pw1, PW);
    round_copy<<<(NL * ND * ND + 255) / 256, 256>>>(wo, WOT, NL * ND * ND);
    round_copy<<<(NL * ND * NFF + 255) / 256, 256>>>(fw1, F1T, NL * ND * NFF);
    round_copy<<<(NL * NFF * ND + 255) / 256, 256>>>(fw2, F2T, NL * NFF * ND);
    round_copy<<<(NL * NREL * NDK + 255) / 256, 256>>>(rel, RELT, NL * NREL * NDK);

    embed_kernel<<<NBS, 128>>>(te, pe, ids, X);

    for (int l = 0; l < NL; l++) {
        const size_t wOff = (size_t)l * ND * ND;
        const size_t dOff = (size_t)l * ND;
        ln_kernel<<<NBS / 8, 256>>>(X, HB, g1 + dOff, b1 + dOff);
        run_big_gemm(HB, WQKV + (size_t)l * ND * QLD, BQKV + (size_t)l * QLD, nullptr,
                     QKV, NBS, QLD, ND, 0);
        attn_tc_kernel<<<dim3(NS / 128, NH, NB), 128, ATT_SMEM_BYTES>>>(
            QKV, QKV + ND, QKV + 2 * ND, RELT + (size_t)l * NREL * NDK, ids, AB);
        run_big_gemm(AB, WOT + wOff, bo + dOff, X, X, NBS, ND, ND, 2);
        ln_kernel<<<NBS / 8, 256>>>(X, HB, g2 + dOff, b2 + dOff);
        run_big_gemm(HB, F1T + (size_t)l * ND * NFF, fb1 + (size_t)l * NFF, nullptr, FB,
                     NBS, NFF, ND, 1);
        run_big_gemm(FB, F2T + (size_t)l * NFF * ND, fb2 + dOff, X, X, NBS, ND, NFF, 2);
    }

    ln_kernel<<<NBS / 8, 256>>>(X, HB, fg, fbn);

    run_big_gemm(HB, PW, pb1, nullptr, PT, NBS, 384, 384, 3);
    pool_score_kernel<<<(4 * NBS + 3) / 4, 128>>>(PT, pw2, pb2, PS);
    pool_kernel<<<dim3(4, NB), 256>>>(HB, PS, ids, PD);

    run_small_gemm(PD, cw1, cb1, C1, NB, ND, 4 * ND, 1);
    run_small_gemm(C1, cw2, cb2, C2, NB, 192, ND, 1);
    run_small_gemm(C2, cw3, cb3, (float*)d_out, NB, NNC, 192, 0);
}